// round 2
// baseline (speedup 1.0000x reference)
#include <cuda_runtime.h>
#include <cuda_bf16.h>
#include <math.h>

#define BB 16
#define SS 512
#define EE 256
#define HH 8
#define DD 32
#define TOK (BB*SS)
#define NEGBIG -1e30f

// ---------------- scratch ----------------
__device__ float g_in2E [TOK*2*EE];
__device__ float g_query[TOK*EE];
__device__ float g_x    [TOK*EE];
__device__ float g_cg   [TOK*EE];
__device__ float g_gg   [TOK*EE];
__device__ float g_pq   [TOK*EE];
__device__ float g_pk   [TOK*EE];
__device__ float g_pv   [TOK*EE];
__device__ float g_q    [TOK*EE];
__device__ float g_k    [TOK*EE];
__device__ float g_v    [TOK*EE];
__device__ float g_out0 [TOK*EE];
__device__ float g_outF [TOK*EE];
__device__ float g_rel  [(size_t)BB*SS*SS];
__device__ float g_time [(size_t)BB*SS*SS];

// ---------------- gather ----------------
__global__ void gather_kernel(const float* __restrict__ item_emb,
                              const int* __restrict__ item_inputs,
                              const int* __restrict__ label_inputs,
                              const int* __restrict__ item_ids)
{
    int tok = blockIdx.x;
    int t   = threadIdx.x;
    int idx = item_inputs[tok];
    int qid = item_ids[tok];
    float lab = (float)label_inputs[tok];
    float ie = item_emb[(size_t)idx*EE + t];
    g_in2E[(size_t)tok*2*EE + t]      = ie * lab;
    g_in2E[(size_t)tok*2*EE + EE + t] = ie * (1.0f - lab);
    g_query[(size_t)tok*EE + t] = item_emb[(size_t)qid*EE + t];
}

// ---------------- SGEMM C = epi(A[M,K]@B[K,N] + bias) ----------------
#define GBM 64
#define GBN 64
#define GBK 16
__global__ void sgemm_epi(const float* __restrict__ A, const float* __restrict__ Bm,
                          const float* __restrict__ bias, float* __restrict__ C,
                          int M, int N, int K, int epi)
{
    __shared__ float As[GBK][GBM];
    __shared__ float Bs[GBK][GBN];
    int bx = blockIdx.x, by = blockIdx.y;
    int tid = threadIdx.x;
    int tcol = tid & 15, trow = tid >> 4;
    int aRow = tid >> 2;
    int aCol = (tid & 3) << 2;
    int bRow = tid >> 4;
    int bCol = (tid & 15) << 2;
    const float* Ab = A + (size_t)(by*GBM)*K;
    const float* Bb = Bm + bx*GBN;
    float acc[4][4] = {};
    for (int k0 = 0; k0 < K; k0 += GBK) {
        float4 av = *reinterpret_cast<const float4*>(Ab + (size_t)aRow*K + k0 + aCol);
        As[aCol+0][aRow] = av.x; As[aCol+1][aRow] = av.y;
        As[aCol+2][aRow] = av.z; As[aCol+3][aRow] = av.w;
        float4 bv = *reinterpret_cast<const float4*>(Bb + (size_t)(k0+bRow)*N + bCol);
        *reinterpret_cast<float4*>(&Bs[bRow][bCol]) = bv;
        __syncthreads();
        #pragma unroll
        for (int kk = 0; kk < GBK; kk++) {
            float ar[4], br[4];
            #pragma unroll
            for (int m = 0; m < 4; m++) ar[m] = As[kk][trow*4+m];
            #pragma unroll
            for (int n = 0; n < 4; n++) br[n] = Bs[kk][tcol*4+n];
            #pragma unroll
            for (int m = 0; m < 4; m++)
                #pragma unroll
                for (int n = 0; n < 4; n++)
                    acc[m][n] += ar[m]*br[n];
        }
        __syncthreads();
    }
    #pragma unroll
    for (int m = 0; m < 4; m++) {
        int row = by*GBM + trow*4 + m;
        #pragma unroll
        for (int n = 0; n < 4; n++) {
            int col = bx*GBN + tcol*4 + n;
            float v = acc[m][n];
            if (bias) v += bias[col];
            if (epi == 1) v = fmaxf(v, 0.0f);
            else if (epi == 2) v = 1.0f/(1.0f + expf(-v));
            C[(size_t)row*N + col] = v;
        }
    }
}

// ---------------- reorder [tok,e] -> [B*H, S, D] ----------------
__global__ void reorder_bhsd(const float* __restrict__ in, float* __restrict__ out)
{
    int tok = blockIdx.x;
    int b = tok >> 9, s = tok & 511;
    int e = threadIdx.x;
    int h = e >> 5, d = e & 31;
    out[(((size_t)(b*HH+h)*SS) + s)*DD + d] = in[(size_t)tok*EE + e];
}

// ---------------- row softmax: rel (mode0) / time (mode1) ----------------
__global__ void rowsm_kernel(const float* __restrict__ src, float* __restrict__ dst, int mode)
{
    int row = blockIdx.x;
    int i = row & (SS-1);
    int t = threadIdx.x;
    __shared__ float shm[8], shs[8];
    const float* sr = src + (size_t)row*SS;
    int j0 = t, j1 = t + 256;
    float v0, v1;
    if (mode == 0) {
        float r0 = (j0 <= i) ? sr[j0] : 0.0f;
        float r1 = (j1 <= i) ? sr[j1] : 0.0f;
        v0 = (r0 == 0.0f) ? -1e5f : r0;
        v1 = (r1 == 0.0f) ? -1e5f : r1;
    } else {
        v0 = (j0 <= i) ? expf(-fabsf(sr[j0])) : -1e5f;
        v1 = (j1 <= i) ? expf(-fabsf(sr[j1])) : -1e5f;
    }
    int lane = t & 31, w = t >> 5;
    float m = fmaxf(v0, v1);
    #pragma unroll
    for (int o = 16; o; o >>= 1) m = fmaxf(m, __shfl_xor_sync(0xffffffffu, m, o));
    if (lane == 0) shm[w] = m;
    __syncthreads();
    m = shm[0];
    #pragma unroll
    for (int k = 1; k < 8; k++) m = fmaxf(m, shm[k]);
    float e0 = expf(v0 - m), e1 = expf(v1 - m);
    float s = e0 + e1;
    #pragma unroll
    for (int o = 16; o; o >>= 1) s += __shfl_xor_sync(0xffffffffu, s, o);
    if (lane == 0) shs[w] = s;
    __syncthreads();
    s = 0.0f;
    #pragma unroll
    for (int k = 0; k < 8; k++) s += shs[k];
    float inv = 1.0f / s;
    dst[(size_t)row*SS + j0] = e0*inv;
    dst[(size_t)row*SS + j1] = e1*inv;
}

// ---------------- attention tile: 32 query rows / block ----------------
#define ATT_SMEM ((32*512 + 32*33 + 64*33 + 320 + 320 + 32)*4)
__global__ void attn_tile_kernel(const float* __restrict__ qh, const float* __restrict__ kh,
                                 const float* __restrict__ vh,
                                 const float* __restrict__ posK, const float* __restrict__ posV,
                                 const float* __restrict__ l1p, const float* __restrict__ l2p,
                                 float* __restrict__ out,
                                 const float* __restrict__ out0_in,
                                 float* __restrict__ attn_out,
                                 int li)
{
    extern __shared__ float smf[];
    float* sc   = smf;                  // 32*512
    float* qs   = sc + 32*512;          // 32*33
    float* ks   = qs + 32*33;           // 64*33
    float* qpk  = ks + 64*33;           // 320
    float* pvw  = qpk + 320;            // 320
    float* rinv = pvw + 320;            // 32

    int it = blockIdx.x;
    int bh = blockIdx.y;
    int b = bh >> 3, h = bh & 7;
    int t = threadIdx.x;
    int i0 = it * 32;
    int jact = (it/2 + 1) * 64;
    int ntile = jact >> 6;
    float l1 = l1p[0], l2 = l2p[0];
    float ca = (1.f-l1)*(1.f-l2), cb = l1*(1.f-l2), cc = l2;
    const float* qbase = qh + (size_t)bh*SS*DD;
    const float* kbase = kh + (size_t)bh*SS*DD;
    const float* vbase = vh + (size_t)bh*SS*DD;

    for (int f = t; f < 32*32; f += 256) {
        int ii = f >> 5, d = f & 31;
        qs[ii*33 + d] = qbase[(size_t)(i0+ii)*DD + d];
    }
    for (int f = t; f < 320; f += 256) pvw[f] = 0.0f;
    __syncthreads();
    for (int f = t; f < 320; f += 256) {
        int ii = f / 10, p = f % 10;
        float s = 0.f;
        #pragma unroll
        for (int d = 0; d < 32; d++) s += qs[ii*33+d] * posK[p*32+d];
        qpk[f] = s;
    }

    int ty = t >> 4, tx = t & 15;
    const float scale = 0.17677669529663687f;   // 1/sqrt(32)
    for (int jt = 0; jt < ntile; jt++) {
        int j0 = jt*64;
        __syncthreads();
        for (int f = t; f < 64*32; f += 256) {
            int jj = f >> 5, d = f & 31;
            ks[jj*33 + d] = kbase[(size_t)(j0+jj)*DD + d];
        }
        __syncthreads();
        float ac[2][4] = {};
        #pragma unroll
        for (int d = 0; d < 32; d++) {
            float a0 = qs[(ty*2+0)*33 + d];
            float a1 = qs[(ty*2+1)*33 + d];
            #pragma unroll
            for (int n = 0; n < 4; n++) {
                float bv = ks[(tx*4+n)*33 + d];
                ac[0][n] += a0*bv;
                ac[1][n] += a1*bv;
            }
        }
        #pragma unroll
        for (int r = 0; r < 2; r++) {
            int ii = ty*2 + r, i = i0 + ii;
            #pragma unroll
            for (int n = 0; n < 4; n++) {
                int j = j0 + tx*4 + n;
                float v;
                if (j <= i) v = (ac[r][n] + qpk[ii*10 + min(i-j, 9)]) * scale;
                else        v = NEGBIG;
                sc[ii*512 + j] = v;
            }
        }
    }
    __syncthreads();

    // softmax + blend + posV buckets: warp w owns rows w*4..w*4+3
    int w = t >> 5, lane = t & 31;
    for (int ii = w*4; ii < w*4 + 4; ii++) {
        int i = i0 + ii;
        float m = NEGBIG;
        for (int j = lane; j < jact; j += 32) m = fmaxf(m, sc[ii*512 + j]);
        #pragma unroll
        for (int o = 16; o; o >>= 1) m = fmaxf(m, __shfl_xor_sync(0xffffffffu, m, o));
        float s = 0.f;
        for (int j = lane; j < jact; j += 32) {
            float e = expf(sc[ii*512 + j] - m);
            sc[ii*512 + j] = e;
            s += e;
        }
        #pragma unroll
        for (int o = 16; o; o >>= 1) s += __shfl_xor_sync(0xffffffffu, s, o);
        float ri = 1.0f / s;
        const float* relrow = g_rel  + (size_t)(b*SS + i)*SS;
        const float* trow   = g_time + (size_t)(b*SS + i)*SS;
        float unif = 1.0f / (float)(i + 1);
        float b9 = 0.f;
        for (int j = lane; j < jact; j += 32) {
            float psm = sc[ii*512 + j] * ri;
            float tv = (li == 0) ? trow[j] : ((j <= i) ? unif : 0.0f);
            float pf = ca*psm + cb*relrow[j] + cc*tv;
            sc[ii*512 + j] = pf;
            if (attn_out) attn_out[((size_t)bh*SS + i)*SS + j] = pf;
            int dist = i - j;
            if (dist >= 0 && dist < 9) pvw[ii*10 + dist] = pf;
            else if (dist >= 9) b9 += pf;
        }
        #pragma unroll
        for (int o = 16; o; o >>= 1) b9 += __shfl_xor_sync(0xffffffffu, b9, o);
        if (lane == 0) pvw[ii*10 + 9] = b9;
    }
    if (attn_out) {
        for (int f = t; f < 32*(SS - jact); f += 256) {
            int ii = f / (SS - jact);
            int j  = jact + f % (SS - jact);
            attn_out[((size_t)bh*SS + (i0+ii))*SS + j] = 0.0f;
        }
    }
    __syncthreads();

    // PV: rows ty*2..+1, dims tx*2..+1
    float o00=0, o01=0, o10=0, o11=0;
    int r0 = ty*2, r1 = ty*2+1, d0 = tx*2, d1 = tx*2+1;
    for (int jt = 0; jt < ntile; jt++) {
        int j0 = jt*64;
        __syncthreads();
        for (int f = t; f < 64*32; f += 256) {
            int jj = f >> 5, d = f & 31;
            ks[jj*33 + d] = vbase[(size_t)(j0+jj)*DD + d];
        }
        __syncthreads();
        #pragma unroll 4
        for (int jj = 0; jj < 64; jj++) {
            int j = j0 + jj;
            float p0 = sc[r0*512 + j];
            float p1 = sc[r1*512 + j];
            float v0 = ks[jj*33 + d0];
            float v1 = ks[jj*33 + d1];
            o00 += p0*v0; o01 += p0*v1;
            o10 += p1*v0; o11 += p1*v1;
        }
    }
    float accs[2][2] = {{o00,o01},{o10,o11}};
    #pragma unroll
    for (int r = 0; r < 2; r++) {
        int ii = ty*2 + r;
        int tok = b*SS + i0 + ii;
        #pragma unroll
        for (int dd = 0; dd < 2; dd++) {
            int d = tx*2 + dd;
            int e = h*DD + d;
            float acc = accs[r][dd];
            #pragma unroll
            for (int p = 0; p < 10; p++) acc += pvw[ii*10 + p] * posV[p*32 + d];
            float val = g_gg[(size_t)tok*EE + e] + (1.0f - g_cg[(size_t)tok*EE + e]) * acc;
            if (li == 0) out[(size_t)tok*EE + e] = val;
            else         out[(size_t)tok*EE + e] = out0_in[(size_t)tok*EE + e] + fmaxf(val, 0.0f);
        }
    }
}

// ---------------- final logits ----------------
__global__ void logits_kernel(const float* __restrict__ x, const float* __restrict__ wv,
                              const float* __restrict__ bv, float* __restrict__ out)
{
    int w = threadIdx.x >> 5, lane = threadIdx.x & 31;
    int tok = blockIdx.x*8 + w;
    float s = 0.f;
    for (int j = lane; j < EE; j += 32) s += x[(size_t)tok*EE + j] * wv[j];
    #pragma unroll
    for (int o = 16; o; o >>= 1) s += __shfl_xor_sync(0xffffffffu, s, o);
    if (lane == 0) out[tok] = s + bv[0];
}

extern "C" void kernel_launch(void* const* d_in, const int* in_sizes, int n_in,
                              void* d_out, int out_size)
{
    // metadata order: skill_nums, q_matrix, item_inputs, label_inputs, item_ids,
    // rel, timestamp, item_emb, pos_key_emb, pos_value_emb, Wc, Wg, lin_in_w,
    // lin_in_b, Wq, bq, Wk, bk, Wv, bv, l1, l2, lin_out_w, lin_out_b
    const int*   item_inputs  = (const int*)  d_in[2];
    const int*   label_inputs = (const int*)  d_in[3];
    const int*   item_ids     = (const int*)  d_in[4];
    const float* rel          = (const float*)d_in[5];
    const float* timestamp    = (const float*)d_in[6];
    const float* item_emb     = (const float*)d_in[7];
    const float* posK         = (const float*)d_in[8];
    const float* posV         = (const float*)d_in[9];
    const float* Wc           = (const float*)d_in[10];
    const float* Wg           = (const float*)d_in[11];
    const float* lin_in_w     = (const float*)d_in[12];
    const float* lin_in_b     = (const float*)d_in[13];
    const float* Wq           = (const float*)d_in[14];
    const float* bq           = (const float*)d_in[15];
    const float* Wk           = (const float*)d_in[16];
    const float* bk           = (const float*)d_in[17];
    const float* Wv           = (const float*)d_in[18];
    const float* bv           = (const float*)d_in[19];
    const float* l1           = (const float*)d_in[20];
    const float* l2           = (const float*)d_in[21];
    const float* lin_out_w    = (const float*)d_in[22];
    const float* lin_out_b    = (const float*)d_in[23];
    float* out = (float*)d_out;
    float* attn_out = out + TOK;   // [16,8,512,512] after [16,512,1] logits

    static int attr_done = 0;
    if (!attr_done) {
        cudaFuncSetAttribute(attn_tile_kernel,
                             cudaFuncAttributeMaxDynamicSharedMemorySize, ATT_SMEM);
        attr_done = 1;
    }

    float *p_in2E, *p_query, *p_x, *p_cg, *p_gg, *p_pq, *p_pk, *p_pv;
    float *p_q, *p_k, *p_v, *p_out0, *p_outF, *p_rel, *p_time;
    cudaGetSymbolAddress((void**)&p_in2E,  g_in2E);
    cudaGetSymbolAddress((void**)&p_query, g_query);
    cudaGetSymbolAddress((void**)&p_x,     g_x);
    cudaGetSymbolAddress((void**)&p_cg,    g_cg);
    cudaGetSymbolAddress((void**)&p_gg,    g_gg);
    cudaGetSymbolAddress((void**)&p_pq,    g_pq);
    cudaGetSymbolAddress((void**)&p_pk,    g_pk);
    cudaGetSymbolAddress((void**)&p_pv,    g_pv);
    cudaGetSymbolAddress((void**)&p_q,     g_q);
    cudaGetSymbolAddress((void**)&p_k,     g_k);
    cudaGetSymbolAddress((void**)&p_v,     g_v);
    cudaGetSymbolAddress((void**)&p_out0,  g_out0);
    cudaGetSymbolAddress((void**)&p_outF,  g_outF);
    cudaGetSymbolAddress((void**)&p_rel,   g_rel);
    cudaGetSymbolAddress((void**)&p_time,  g_time);

    dim3 g512(EE/GBN, TOK/GBM);   // (4,128)
    dim3 gatt(16, BB*HH);         // (16,128)

    gather_kernel<<<TOK, EE>>>(item_emb, item_inputs, label_inputs, item_ids);
    sgemm_epi<<<g512, 256>>>(p_in2E,  lin_in_w, lin_in_b, p_x,  TOK, EE, 2*EE, 1);
    sgemm_epi<<<g512, 256>>>(p_query, Wc,       nullptr,  p_cg, TOK, EE, EE,   2);
    sgemm_epi<<<g512, 256>>>(p_query, Wg,       nullptr,  p_gg, TOK, EE, EE,   2);
    rowsm_kernel<<<BB*SS, 256>>>(rel,       p_rel,  0);
    rowsm_kernel<<<BB*SS, 256>>>(timestamp, p_time, 1);

    // layer 0
    sgemm_epi<<<g512, 256>>>(p_query, Wq,       bq,       p_pq, TOK, EE, EE, 0);
    sgemm_epi<<<g512, 256>>>(p_x,     Wk,       bk,       p_pk, TOK, EE, EE, 0);
    sgemm_epi<<<g512, 256>>>(p_x,     Wv,       bv,       p_pv, TOK, EE, EE, 0);
    reorder_bhsd<<<TOK, EE>>>(p_pq, p_q);
    reorder_bhsd<<<TOK, EE>>>(p_pk, p_k);
    reorder_bhsd<<<TOK, EE>>>(p_pv, p_v);
    attn_tile_kernel<<<gatt, 256, ATT_SMEM>>>(p_q, p_k, p_v, posK, posV, l1, l2,
                                              p_out0, nullptr, nullptr, 0);
    // layer 1
    sgemm_epi<<<g512, 256>>>(p_query, Wq + EE*EE, bq + EE, p_pq, TOK, EE, EE, 0);
    sgemm_epi<<<g512, 256>>>(p_out0,  Wk + EE*EE, bk + EE, p_pk, TOK, EE, EE, 0);
    sgemm_epi<<<g512, 256>>>(p_out0,  Wv + EE*EE, bv + EE, p_pv, TOK, EE, EE, 0);
    reorder_bhsd<<<TOK, EE>>>(p_pq, p_q);
    reorder_bhsd<<<TOK, EE>>>(p_pk, p_k);
    reorder_bhsd<<<TOK, EE>>>(p_pv, p_v);
    attn_tile_kernel<<<gatt, 256, ATT_SMEM>>>(p_q, p_k, p_v, posK, posV, l1, l2,
                                              p_outF, p_out0, attn_out, 1);

    logits_kernel<<<TOK/8, 256>>>(p_outF, lin_out_w, lin_out_b, out);
}

// round 3
// speedup vs baseline: 1.1392x; 1.1392x over previous
#include <cuda_runtime.h>
#include <cuda_bf16.h>
#include <math.h>
#include <stdint.h>

#define BB 16
#define SS 512
#define EE 256
#define HH 8
#define DD 32
#define TOK (BB*SS)
#define NEGBIG -1e30f

// ---------------- scratch ----------------
__device__ float g_in2E [TOK*2*EE];
__device__ float g_query[TOK*EE];
__device__ float g_x    [TOK*EE];
__device__ float g_cg   [TOK*EE];
__device__ float g_gg   [TOK*EE];
__device__ float g_q    [TOK*EE];
__device__ float g_k    [TOK*EE];
__device__ float g_v    [TOK*EE];
__device__ float g_out0 [TOK*EE];
__device__ float g_outF [TOK*EE];
__device__ float g_rel  [(size_t)BB*SS*SS];
__device__ float g_time [(size_t)BB*SS*SS];

// ---------------- gather ----------------
__global__ void gather_kernel(const float* __restrict__ item_emb,
                              const int* __restrict__ item_inputs,
                              const int* __restrict__ label_inputs,
                              const int* __restrict__ item_ids)
{
    int tok = blockIdx.x;
    int t   = threadIdx.x;
    int idx = item_inputs[tok];
    int qid = item_ids[tok];
    float lab = (float)label_inputs[tok];
    float ie = item_emb[(size_t)idx*EE + t];
    g_in2E[(size_t)tok*2*EE + t]      = ie * lab;
    g_in2E[(size_t)tok*2*EE + EE + t] = ie * (1.0f - lab);
    g_query[(size_t)tok*EE + t] = item_emb[(size_t)qid*EE + t];
}

// ---------------- TF32 tensor-core GEMM ----------------
// C[M,N] = epi(A[M,K] @ B[K,N] + bias).  Block tile 128x64, 8 warps (4x2),
// warp tile 32x32 (2 m16 x 4 n8 mma tiles).  BK=16 (2 k8 steps).
// Fragment-major smem layout: per (kstep, tile, lane) the lane's mma regs
// are contiguous -> LDS.128 for A frags, LDS.64 for B frags, no ldmatrix.
// epi: 0=+bias, 1=relu(+bias), 2=sigmoid.  bhsd: remap [tok,e]->[B,H,S,D].
__device__ __forceinline__ uint32_t f2tf32(float v) {
    uint32_t u;
    asm volatile("cvt.rna.tf32.f32 %0, %1;" : "=r"(u) : "f"(v));
    return u;
}

__global__ __launch_bounds__(256, 2)
void tf32gemm(const float* __restrict__ A, const float* __restrict__ Bm,
              const float* __restrict__ bias, float* __restrict__ C,
              int M, int N, int K, int epi, int bhsd)
{
    __shared__ uint32_t As[2048];   // 2 ks * 8 mt * 32 lanes * 4 regs
    __shared__ uint32_t Bs[1024];   // 2 ks * 8 nt * 32 lanes * 2 regs
    int t = threadIdx.x;
    int lane = t & 31, wid = t >> 5;
    int wm = wid >> 1, wn = wid & 1;      // warp grid 4x2
    int bx = blockIdx.x, by = blockIdx.y;
    int m0 = by * 128, n0 = bx * 64;

    float acc[2][4][4];
    #pragma unroll
    for (int i = 0; i < 2; i++)
        #pragma unroll
        for (int j = 0; j < 4; j++)
            #pragma unroll
            for (int r = 0; r < 4; r++) acc[i][j][r] = 0.0f;

    // copy indices
    int aRow0 = t >> 2;                 // +128 for second
    int aColG = (t & 3) * 4;
    int bRow  = t >> 4;
    int bColG = (t & 15) * 4;

    for (int k0 = 0; k0 < K; k0 += 16) {
        __syncthreads();
        // A tile: 128x16, 2 float4 per thread
        #pragma unroll
        for (int rep = 0; rep < 2; rep++) {
            int row = aRow0 + rep * 64;
            float4 av = *reinterpret_cast<const float4*>(A + (size_t)(m0+row)*K + k0 + aColG);
            float vv[4] = {av.x, av.y, av.z, av.w};
            int mt = row >> 4, mm = row & 15;
            int g = mm & 7, half = mm >> 3;
            #pragma unroll
            for (int j = 0; j < 4; j++) {
                int k = aColG + j;
                int ks = k >> 3, kc = k & 7;
                int cc = kc & 3, hi = kc >> 2;
                As[((ks*8+mt)*32 + g*4+cc)*4 + half + hi*2] = f2tf32(vv[j]);
            }
        }
        // B tile: 16x64, 1 float4 per thread
        {
            float4 bv = *reinterpret_cast<const float4*>(Bm + (size_t)(k0+bRow)*N + n0 + bColG);
            float vv[4] = {bv.x, bv.y, bv.z, bv.w};
            int ks = bRow >> 3, kc = bRow & 7;
            int cc = kc & 3, hi = kc >> 2;
            #pragma unroll
            for (int j = 0; j < 4; j++) {
                int n = bColG + j;
                int nt = n >> 3, g = n & 7;
                Bs[((ks*8+nt)*32 + g*4+cc)*2 + hi] = f2tf32(vv[j]);
            }
        }
        __syncthreads();
        #pragma unroll
        for (int ks = 0; ks < 2; ks++) {
            uint4 af[2];
            uint2 bf[4];
            #pragma unroll
            for (int mi = 0; mi < 2; mi++) {
                int mt = wm*2 + mi;
                af[mi] = reinterpret_cast<const uint4*>(As)[(ks*8+mt)*32 + lane];
            }
            #pragma unroll
            for (int ni = 0; ni < 4; ni++) {
                int nt = wn*4 + ni;
                bf[ni] = reinterpret_cast<const uint2*>(Bs)[(ks*8+nt)*32 + lane];
            }
            #pragma unroll
            for (int mi = 0; mi < 2; mi++)
                #pragma unroll
                for (int ni = 0; ni < 4; ni++) {
                    asm volatile(
                        "mma.sync.aligned.m16n8k8.row.col.f32.tf32.tf32.f32 "
                        "{%0,%1,%2,%3}, {%4,%5,%6,%7}, {%8,%9}, {%0,%1,%2,%3};\n"
                        : "+f"(acc[mi][ni][0]), "+f"(acc[mi][ni][1]),
                          "+f"(acc[mi][ni][2]), "+f"(acc[mi][ni][3])
                        : "r"(af[mi].x), "r"(af[mi].y), "r"(af[mi].z), "r"(af[mi].w),
                          "r"(bf[ni].x), "r"(bf[ni].y));
                }
        }
    }

    // epilogue
    int g = lane >> 2, cq = lane & 3;
    #pragma unroll
    for (int mi = 0; mi < 2; mi++) {
        #pragma unroll
        for (int ni = 0; ni < 4; ni++) {
            #pragma unroll
            for (int r = 0; r < 4; r++) {
                int row = m0 + (wm*2+mi)*16 + g + ((r >> 1) ? 8 : 0);
                int col = n0 + (wn*4+ni)*8 + cq*2 + (r & 1);
                float v = acc[mi][ni][r];
                if (bias) v += bias[col];
                if (epi == 1) v = fmaxf(v, 0.0f);
                else if (epi == 2) v = 1.0f/(1.0f + expf(-v));
                size_t oidx;
                if (bhsd) {
                    int b = row >> 9, s = row & 511;
                    int h = col >> 5, d = col & 31;
                    oidx = (((size_t)(b*HH+h)*SS) + s)*DD + d;
                } else {
                    oidx = (size_t)row*N + col;
                }
                C[oidx] = v;
            }
        }
    }
}

// ---------------- row softmax: rel (mode0) / time (mode1) ----------------
__global__ void rowsm_kernel(const float* __restrict__ src, float* __restrict__ dst, int mode)
{
    int row = blockIdx.x;
    int i = row & (SS-1);
    int t = threadIdx.x;
    __shared__ float shm[8], shs[8];
    const float* sr = src + (size_t)row*SS;
    int j0 = t, j1 = t + 256;
    float v0, v1;
    if (mode == 0) {
        float r0 = (j0 <= i) ? sr[j0] : 0.0f;
        float r1 = (j1 <= i) ? sr[j1] : 0.0f;
        v0 = (r0 == 0.0f) ? -1e5f : r0;
        v1 = (r1 == 0.0f) ? -1e5f : r1;
    } else {
        v0 = (j0 <= i) ? expf(-fabsf(sr[j0])) : -1e5f;
        v1 = (j1 <= i) ? expf(-fabsf(sr[j1])) : -1e5f;
    }
    int lane = t & 31, w = t >> 5;
    float m = fmaxf(v0, v1);
    #pragma unroll
    for (int o = 16; o; o >>= 1) m = fmaxf(m, __shfl_xor_sync(0xffffffffu, m, o));
    if (lane == 0) shm[w] = m;
    __syncthreads();
    m = shm[0];
    #pragma unroll
    for (int k = 1; k < 8; k++) m = fmaxf(m, shm[k]);
    float e0 = expf(v0 - m), e1 = expf(v1 - m);
    float s = e0 + e1;
    #pragma unroll
    for (int o = 16; o; o >>= 1) s += __shfl_xor_sync(0xffffffffu, s, o);
    if (lane == 0) shs[w] = s;
    __syncthreads();
    s = 0.0f;
    #pragma unroll
    for (int k = 0; k < 8; k++) s += shs[k];
    float inv = 1.0f / s;
    dst[(size_t)row*SS + j0] = e0*inv;
    dst[(size_t)row*SS + j1] = e1*inv;
}

// ---------------- attention tile: 32 query rows / block ----------------
#define ATT_SMEM ((32*512 + 32*33 + 64*33 + 320 + 320 + 32)*4)
__global__ void attn_tile_kernel(const float* __restrict__ qh, const float* __restrict__ kh,
                                 const float* __restrict__ vh,
                                 const float* __restrict__ posK, const float* __restrict__ posV,
                                 const float* __restrict__ l1p, const float* __restrict__ l2p,
                                 float* __restrict__ out,
                                 const float* __restrict__ out0_in,
                                 float* __restrict__ attn_out,
                                 int li)
{
    extern __shared__ float smf[];
    float* sc   = smf;                  // 32*512
    float* qs   = sc + 32*512;          // 32*33
    float* ks   = qs + 32*33;           // 64*33
    float* qpk  = ks + 64*33;           // 320
    float* pvw  = qpk + 320;            // 320

    int it = blockIdx.x;
    int bh = blockIdx.y;
    int b = bh >> 3, h = bh & 7;
    int t = threadIdx.x;
    int i0 = it * 32;
    int jact = (it/2 + 1) * 64;
    int ntile = jact >> 6;
    float l1 = l1p[0], l2 = l2p[0];
    float ca = (1.f-l1)*(1.f-l2), cb = l1*(1.f-l2), cc = l2;
    const float* qbase = qh + (size_t)bh*SS*DD;
    const float* kbase = kh + (size_t)bh*SS*DD;
    const float* vbase = vh + (size_t)bh*SS*DD;

    for (int f = t; f < 32*32; f += 256) {
        int ii = f >> 5, d = f & 31;
        qs[ii*33 + d] = qbase[(size_t)(i0+ii)*DD + d];
    }
    __syncthreads();
    for (int f = t; f < 320; f += 256) {
        int ii = f / 10, p = f % 10;
        float s = 0.f;
        #pragma unroll
        for (int d = 0; d < 32; d++) s += qs[ii*33+d] * posK[p*32+d];
        qpk[f] = s;
    }

    int ty = t >> 4, tx = t & 15;
    const float scale = 0.17677669529663687f;   // 1/sqrt(32)
    for (int jt = 0; jt < ntile; jt++) {
        int j0 = jt*64;
        __syncthreads();
        for (int f = t; f < 64*32; f += 256) {
            int jj = f >> 5, d = f & 31;
            ks[jj*33 + d] = kbase[(size_t)(j0+jj)*DD + d];
        }
        __syncthreads();
        float ac[2][4] = {};
        #pragma unroll
        for (int d = 0; d < 32; d++) {
            float a0 = qs[(ty*2+0)*33 + d];
            float a1 = qs[(ty*2+1)*33 + d];
            #pragma unroll
            for (int n = 0; n < 4; n++) {
                float bv = ks[(tx*4+n)*33 + d];
                ac[0][n] += a0*bv;
                ac[1][n] += a1*bv;
            }
        }
        #pragma unroll
        for (int r = 0; r < 2; r++) {
            int ii = ty*2 + r, i = i0 + ii;
            #pragma unroll
            for (int n = 0; n < 4; n++) {
                int j = j0 + tx*4 + n;
                float v;
                if (j <= i) v = (ac[r][n] + qpk[ii*10 + min(i-j, 9)]) * scale;
                else        v = NEGBIG;
                sc[ii*512 + j] = v;
            }
        }
    }
    __syncthreads();

    // softmax + blend + posV buckets: warp w owns rows w*4..w*4+3
    int w = t >> 5, lane = t & 31;
    for (int ii = w*4; ii < w*4 + 4; ii++) {
        int i = i0 + ii;
        float m = NEGBIG;
        for (int j = lane; j < jact; j += 32) m = fmaxf(m, sc[ii*512 + j]);
        #pragma unroll
        for (int o = 16; o; o >>= 1) m = fmaxf(m, __shfl_xor_sync(0xffffffffu, m, o));
        float s = 0.f;
        for (int j = lane; j < jact; j += 32) {
            float e = expf(sc[ii*512 + j] - m);
            sc[ii*512 + j] = e;
            s += e;
        }
        #pragma unroll
        for (int o = 16; o; o >>= 1) s += __shfl_xor_sync(0xffffffffu, s, o);
        float ri = 1.0f / s;
        const float* relrow = g_rel  + (size_t)(b*SS + i)*SS;
        const float* trow   = g_time + (size_t)(b*SS + i)*SS;
        float unif = 1.0f / (float)(i + 1);
        float b9 = 0.f;
        for (int j = lane; j < jact; j += 32) {
            float psm = sc[ii*512 + j] * ri;
            float tv = (li == 0) ? trow[j] : ((j <= i) ? unif : 0.0f);
            float pf = ca*psm + cb*relrow[j] + cc*tv;
            sc[ii*512 + j] = pf;
            if (attn_out) attn_out[((size_t)bh*SS + i)*SS + j] = pf;
            int dist = i - j;
            if (dist >= 0 && dist < 9) pvw[ii*10 + dist] = pf;
            else if (dist >= 9) b9 += pf;
        }
        #pragma unroll
        for (int o = 16; o; o >>= 1) b9 += __shfl_xor_sync(0xffffffffu, b9, o);
        if (lane == 0) pvw[ii*10 + 9] = b9;
    }
    if (attn_out) {
        for (int f = t; f < 32*(SS - jact); f += 256) {
            int ii = f / (SS - jact);
            int j  = jact + f % (SS - jact);
            attn_out[((size_t)bh*SS + (i0+ii))*SS + j] = 0.0f;
        }
    }
    __syncthreads();

    // PV: rows ty*2..+1, dims tx*2..+1
    float o00=0, o01=0, o10=0, o11=0;
    int r0 = ty*2, r1 = ty*2+1, d0 = tx*2, d1 = tx*2+1;
    for (int jt = 0; jt < ntile; jt++) {
        int j0 = jt*64;
        __syncthreads();
        for (int f = t; f < 64*32; f += 256) {
            int jj = f >> 5, d = f & 31;
            ks[jj*33 + d] = vbase[(size_t)(j0+jj)*DD + d];
        }
        __syncthreads();
        #pragma unroll 4
        for (int jj = 0; jj < 64; jj++) {
            int j = j0 + jj;
            float p0 = sc[r0*512 + j];
            float p1 = sc[r1*512 + j];
            float v0 = ks[jj*33 + d0];
            float v1 = ks[jj*33 + d1];
            o00 += p0*v0; o01 += p0*v1;
            o10 += p1*v0; o11 += p1*v1;
        }
    }
    float accs[2][2] = {{o00,o01},{o10,o11}};
    #pragma unroll
    for (int r = 0; r < 2; r++) {
        int ii = ty*2 + r;
        int tok = b*SS + i0 + ii;
        #pragma unroll
        for (int dd = 0; dd < 2; dd++) {
            int d = tx*2 + dd;
            int e = h*DD + d;
            float acc = accs[r][dd];
            #pragma unroll
            for (int p = 0; p < 10; p++) acc += pvw[ii*10 + p] * posV[p*32 + d];
            float val = g_gg[(size_t)tok*EE + e] + (1.0f - g_cg[(size_t)tok*EE + e]) * acc;
            if (li == 0) out[(size_t)tok*EE + e] = val;
            else         out[(size_t)tok*EE + e] = out0_in[(size_t)tok*EE + e] + fmaxf(val, 0.0f);
        }
    }
}

// ---------------- final logits ----------------
__global__ void logits_kernel(const float* __restrict__ x, const float* __restrict__ wv,
                              const float* __restrict__ bv, float* __restrict__ out)
{
    int w = threadIdx.x >> 5, lane = threadIdx.x & 31;
    int tok = blockIdx.x*8 + w;
    float s = 0.f;
    for (int j = lane; j < EE; j += 32) s += x[(size_t)tok*EE + j] * wv[j];
    #pragma unroll
    for (int o = 16; o; o >>= 1) s += __shfl_xor_sync(0xffffffffu, s, o);
    if (lane == 0) out[tok] = s + bv[0];
}

extern "C" void kernel_launch(void* const* d_in, const int* in_sizes, int n_in,
                              void* d_out, int out_size)
{
    const int*   item_inputs  = (const int*)  d_in[2];
    const int*   label_inputs = (const int*)  d_in[3];
    const int*   item_ids     = (const int*)  d_in[4];
    const float* rel          = (const float*)d_in[5];
    const float* timestamp    = (const float*)d_in[6];
    const float* item_emb     = (const float*)d_in[7];
    const float* posK         = (const float*)d_in[8];
    const float* posV         = (const float*)d_in[9];
    const float* Wc           = (const float*)d_in[10];
    const float* Wg           = (const float*)d_in[11];
    const float* lin_in_w     = (const float*)d_in[12];
    const float* lin_in_b     = (const float*)d_in[13];
    const float* Wq           = (const float*)d_in[14];
    const float* bq           = (const float*)d_in[15];
    const float* Wk           = (const float*)d_in[16];
    const float* bk           = (const float*)d_in[17];
    const float* Wv           = (const float*)d_in[18];
    const float* bv           = (const float*)d_in[19];
    const float* l1           = (const float*)d_in[20];
    const float* l2           = (const float*)d_in[21];
    const float* lin_out_w    = (const float*)d_in[22];
    const float* lin_out_b    = (const float*)d_in[23];
    float* out = (float*)d_out;
    float* attn_out = out + TOK;   // [16,8,512,512] after [16,512,1]

    static int attr_done = 0;
    if (!attr_done) {
        cudaFuncSetAttribute(attn_tile_kernel,
                             cudaFuncAttributeMaxDynamicSharedMemorySize, ATT_SMEM);
        attr_done = 1;
    }

    float *p_in2E, *p_query, *p_x, *p_cg, *p_gg;
    float *p_q, *p_k, *p_v, *p_out0, *p_outF, *p_rel, *p_time;
    cudaGetSymbolAddress((void**)&p_in2E,  g_in2E);
    cudaGetSymbolAddress((void**)&p_query, g_query);
    cudaGetSymbolAddress((void**)&p_x,     g_x);
    cudaGetSymbolAddress((void**)&p_cg,    g_cg);
    cudaGetSymbolAddress((void**)&p_gg,    g_gg);
    cudaGetSymbolAddress((void**)&p_q,     g_q);
    cudaGetSymbolAddress((void**)&p_k,     g_k);
    cudaGetSymbolAddress((void**)&p_v,     g_v);
    cudaGetSymbolAddress((void**)&p_out0,  g_out0);
    cudaGetSymbolAddress((void**)&p_outF,  g_outF);
    cudaGetSymbolAddress((void**)&p_rel,   g_rel);
    cudaGetSymbolAddress((void**)&p_time,  g_time);

    dim3 gg(EE/64, TOK/128);      // (4,64)
    dim3 gatt(16, BB*HH);         // (16,128)

    gather_kernel<<<TOK, EE>>>(item_emb, item_inputs, label_inputs, item_ids);
    tf32gemm<<<gg, 256>>>(p_in2E,  lin_in_w, lin_in_b, p_x,  TOK, EE, 2*EE, 1, 0);
    tf32gemm<<<gg, 256>>>(p_query, Wc,       nullptr,  p_cg, TOK, EE, EE,   2, 0);
    tf32gemm<<<gg, 256>>>(p_query, Wg,       nullptr,  p_gg, TOK, EE, EE,   2, 0);
    rowsm_kernel<<<BB*SS, 256>>>(rel,       p_rel,  0);
    rowsm_kernel<<<BB*SS, 256>>>(timestamp, p_time, 1);

    // layer 0
    tf32gemm<<<gg, 256>>>(p_query, Wq, bq, p_q, TOK, EE, EE, 0, 1);
    tf32gemm<<<gg, 256>>>(p_x,     Wk, bk, p_k, TOK, EE, EE, 0, 1);
    tf32gemm<<<gg, 256>>>(p_x,     Wv, bv, p_v, TOK, EE, EE, 0, 1);
    attn_tile_kernel<<<gatt, 256, ATT_SMEM>>>(p_q, p_k, p_v, posK, posV, l1, l2,
                                              p_out0, nullptr, nullptr, 0);
    // layer 1
    tf32gemm<<<gg, 256>>>(p_query, Wq + EE*EE, bq + EE, p_q, TOK, EE, EE, 0, 1);
    tf32gemm<<<gg, 256>>>(p_out0,  Wk + EE*EE, bk + EE, p_k, TOK, EE, EE, 0, 1);
    tf32gemm<<<gg, 256>>>(p_out0,  Wv + EE*EE, bv + EE, p_v, TOK, EE, EE, 0, 1);
    attn_tile_kernel<<<gatt, 256, ATT_SMEM>>>(p_q, p_k, p_v, posK, posV, l1, l2,
                                              p_outF, p_out0, attn_out, 1);

    logits_kernel<<<TOK/8, 256>>>(p_outF, lin_out_w, lin_out_b, out);
}